// round 2
// baseline (speedup 1.0000x reference)
#include <cuda_runtime.h>
#include <cuda_bf16.h>
#include <math_constants.h>

#define T_TOK 8192
#define DIM   256
#define NSLOT 4096
#define FULLM 0xffffffffu

// ---------------- scratch (device globals; no allocation) ----------------
__device__ float g_k[T_TOK * DIM];
__device__ float g_v[T_TOK * DIM];
__device__ float g_q[T_TOK * DIM];
__device__ float g_pmax[4 * T_TOK];
__device__ int   g_pidx[4 * T_TOK];
__device__ unsigned g_info[T_TOK];   // best | novel<<16 | m<<17
__device__ unsigned g_pick[T_TOK];   // slot | novel<<16 | applied<<17
__device__ float g_act[NSLOT];
__device__ float g_kb[NSLOT * DIM];
__device__ float g_vb[NSLOT * DIM];

// ---------------- 1) projections: C[T,256] = X @ W^T + b -----------------
__global__ __launch_bounds__(256) void proj_kernel(
    const float* __restrict__ x,
    const float* __restrict__ Wk, const float* __restrict__ bk,
    const float* __restrict__ Wv, const float* __restrict__ bv,
    const float* __restrict__ Wq, const float* __restrict__ bq)
{
    const float* W; const float* b; float* out;
    if (blockIdx.z == 0)      { W = Wk; b = bk; out = g_k; }
    else if (blockIdx.z == 1) { W = Wv; b = bv; out = g_v; }
    else                      { W = Wq; b = bq; out = g_q; }

    __shared__ float As[64][17];
    __shared__ float Bs[64][17];
    int tid = threadIdx.x;
    int tx = tid & 15, ty = tid >> 4;
    int t0 = blockIdx.x * 64, i0 = blockIdx.y * 64;

    float acc[4][4];
#pragma unroll
    for (int r = 0; r < 4; r++)
#pragma unroll
        for (int c = 0; c < 4; c++) acc[r][c] = 0.f;

    int srow = tid >> 2, sc4 = (tid & 3) * 4;
    for (int kk = 0; kk < DIM; kk += 16) {
        float4 av = *(const float4*)&x[(t0 + srow) * DIM + kk + sc4];
        As[srow][sc4 + 0] = av.x; As[srow][sc4 + 1] = av.y;
        As[srow][sc4 + 2] = av.z; As[srow][sc4 + 3] = av.w;
        float4 bv4 = *(const float4*)&W[(i0 + srow) * DIM + kk + sc4];
        Bs[srow][sc4 + 0] = bv4.x; Bs[srow][sc4 + 1] = bv4.y;
        Bs[srow][sc4 + 2] = bv4.z; Bs[srow][sc4 + 3] = bv4.w;
        __syncthreads();
#pragma unroll
        for (int k = 0; k < 16; k++) {
            float a[4], bb[4];
#pragma unroll
            for (int r = 0; r < 4; r++) a[r] = As[ty * 4 + r][k];
#pragma unroll
            for (int c = 0; c < 4; c++) bb[c] = Bs[tx * 4 + c][k];
#pragma unroll
            for (int r = 0; r < 4; r++)
#pragma unroll
                for (int c = 0; c < 4; c++) acc[r][c] += a[r] * bb[c];
        }
        __syncthreads();
    }
#pragma unroll
    for (int r = 0; r < 4; r++)
#pragma unroll
        for (int c = 0; c < 4; c++)
            out[(t0 + ty * 4 + r) * DIM + i0 + tx * 4 + c] =
                acc[r][c] + b[i0 + tx * 4 + c];
}

// ------- 2) per-token max/argmax of k_all @ keys0^T over a segment -------
__global__ __launch_bounds__(256) void simmax_kernel(const float* __restrict__ keys0)
{
    __shared__ float As[64][17];
    __shared__ float Bs[64][17];
    int tid = threadIdx.x;
    int tx = tid & 15, ty = tid >> 4;
    int t0 = blockIdx.x * 64;
    int seg = blockIdx.y;
    int seg0 = seg * 1024;

    float bmax[4]; int bidx[4];
#pragma unroll
    for (int r = 0; r < 4; r++) { bmax[r] = -CUDART_INF_F; bidx[r] = 0x7fffffff; }

    int srow = tid >> 2, sc4 = (tid & 3) * 4;
    for (int n0 = seg0; n0 < seg0 + 1024; n0 += 64) {
        float acc[4][4];
#pragma unroll
        for (int r = 0; r < 4; r++)
#pragma unroll
            for (int c = 0; c < 4; c++) acc[r][c] = 0.f;
        for (int kk = 0; kk < DIM; kk += 16) {
            float4 av = *(const float4*)&g_k[(t0 + srow) * DIM + kk + sc4];
            As[srow][sc4 + 0] = av.x; As[srow][sc4 + 1] = av.y;
            As[srow][sc4 + 2] = av.z; As[srow][sc4 + 3] = av.w;
            float4 bv4 = *(const float4*)&keys0[(n0 + srow) * DIM + kk + sc4];
            Bs[srow][sc4 + 0] = bv4.x; Bs[srow][sc4 + 1] = bv4.y;
            Bs[srow][sc4 + 2] = bv4.z; Bs[srow][sc4 + 3] = bv4.w;
            __syncthreads();
#pragma unroll
            for (int k = 0; k < 16; k++) {
                float a[4], bb[4];
#pragma unroll
                for (int r = 0; r < 4; r++) a[r] = As[ty * 4 + r][k];
#pragma unroll
                for (int c = 0; c < 4; c++) bb[c] = Bs[tx * 4 + c][k];
#pragma unroll
                for (int r = 0; r < 4; r++)
#pragma unroll
                    for (int c = 0; c < 4; c++) acc[r][c] += a[r] * bb[c];
            }
            __syncthreads();
        }
        // running max in ascending-index encounter order: strict > keeps first
#pragma unroll
        for (int r = 0; r < 4; r++)
#pragma unroll
            for (int c = 0; c < 4; c++) {
                float v = acc[r][c];
                if (v > bmax[r]) { bmax[r] = v; bidx[r] = n0 + tx * 4 + c; }
            }
    }
    // reduce across the 16 lanes that share each row
#pragma unroll
    for (int r = 0; r < 4; r++) {
#pragma unroll
        for (int o = 1; o < 16; o <<= 1) {
            float ov = __shfl_xor_sync(FULLM, bmax[r], o);
            int   oi = __shfl_xor_sync(FULLM, bidx[r], o);
            if (ov > bmax[r] || (ov == bmax[r] && oi < bidx[r])) {
                bmax[r] = ov; bidx[r] = oi;
            }
        }
        if (tx == 0) {
            int t = t0 + ty * 4 + r;
            g_pmax[seg * T_TOK + t] = bmax[r];
            g_pidx[seg * T_TOK + t] = bidx[r];
        }
    }
}

// ------- 3) combine segments -> g_info (best | novel | mask) -------------
__global__ void combine_kernel(const void* __restrict__ maskptr)
{
    int t = blockIdx.x * blockDim.x + threadIdx.x;
    if (t >= T_TOK) return;
    float best = -CUDART_INF_F; int bi = 0;
#pragma unroll
    for (int s = 0; s < 4; s++) {
        float v = g_pmax[s * T_TOK + t];
        int   i = g_pidx[s * T_TOK + t];
        if (v > best) { best = v; bi = i; }   // segments ascend in index
    }
    bool novel = (best * 0.0625f) < 0.5f;
    const unsigned* w = (const unsigned*)maskptr;
    bool bytemode = (w[0] == 0x01010101u);    // bool(u8) all-true vs int/float words
    bool m;
    if (bytemode) m = ((const unsigned char*)maskptr)[t] != 0;
    else          m = (w[t] != 0);
    g_info[t] = (unsigned)bi | (novel ? 0x10000u : 0u) | (m ? 0x20000u : 0u);
}

// ------- 4) sequential scan: slot selection + activation evolution -------
__global__ __launch_bounds__(256) void scan_kernel(const float* __restrict__ act0)
{
    __shared__ __align__(16) float s_act[NSLOT];
    __shared__ __align__(16) float s_gmin[128];
    __shared__ int s_gidx[128];
    int tid = threadIdx.x;
    for (int i = tid; i < NSLOT; i += 256) s_act[i] = act0[i];
    __syncthreads();
    int wid = tid >> 5, lane = tid & 31;
    for (int g = wid; g < 128; g += 8) {
        float v = s_act[g * 32 + lane];
        unsigned mv = __reduce_min_sync(FULLM, __float_as_uint(v));
        unsigned bal = __ballot_sync(FULLM, __float_as_uint(v) == mv);
        if (lane == 0) { s_gmin[g] = __uint_as_float(mv); s_gidx[g] = g * 32 + (__ffs(bal) - 1); }
    }
    __syncthreads();

    if (wid == 0) {
        unsigned myinfo = 0;
        for (int t = 0; t < T_TOK; t++) {
            if ((t & 31) == 0) myinfo = __ldg(&g_info[t + lane]);
            unsigned info = __shfl_sync(FULLM, myinfo, t & 31);
            if (info & 0x20000u) {
                int slot;
                if (info & 0x10000u) {
                    float4 q4 = *(const float4*)&s_gmin[lane * 4];
                    float bv = q4.x; int bg = lane * 4;
                    if (q4.y < bv) { bv = q4.y; bg = lane * 4 + 1; }
                    if (q4.z < bv) { bv = q4.z; bg = lane * 4 + 2; }
                    if (q4.w < bv) { bv = q4.w; bg = lane * 4 + 3; }
                    unsigned mv = __reduce_min_sync(FULLM, __float_as_uint(bv));
                    unsigned bal = __ballot_sync(FULLM, __float_as_uint(bv) == mv);
                    int L = __ffs(bal) - 1;
                    int grp = __shfl_sync(FULLM, bg, L);
                    slot = s_gidx[grp];
                } else {
                    slot = (int)(info & 0xFFFFu);
                }
                float na = fminf(1.0f, s_act[slot] + 0.1f);
                if (lane == 0) s_act[slot] = na;
                __syncwarp();
                int g = slot >> 5;
                float v = s_act[g * 32 + lane];
                unsigned mv2 = __reduce_min_sync(FULLM, __float_as_uint(v));
                unsigned bal2 = __ballot_sync(FULLM, __float_as_uint(v) == mv2);
                if (lane == 0) {
                    s_gmin[g] = __uint_as_float(mv2);
                    s_gidx[g] = g * 32 + (__ffs(bal2) - 1);
                    g_pick[t] = (unsigned)slot | (info & 0x10000u) | 0x20000u;
                }
                __syncwarp();
            } else {
                if (lane == 0) g_pick[t] = 0u;
            }
        }
    }
    __syncthreads();
    for (int i = tid; i < NSLOT; i += 256) g_act[i] = s_act[i];
}

// ------- 5) rebuild kb/vb: replay per-slot EMA in exact time order -------
__global__ __launch_bounds__(256) void rebuild_kernel(
    const float* __restrict__ keys0, const float* __restrict__ values0)
{
    int wid = threadIdx.x >> 5, lane = threadIdx.x & 31;
    int s = blockIdx.x * 8 + wid;
    float kreg[8], vreg[8];
#pragma unroll
    for (int r = 0; r < 8; r++) {
        kreg[r] = keys0[s * DIM + lane + 32 * r];
        vreg[r] = values0[s * DIM + lane + 32 * r];
    }
    for (int base = 0; base < T_TOK; base += 32) {
        unsigned pk = __ldg(&g_pick[base + lane]);
        unsigned match = __ballot_sync(FULLM,
            (pk & 0x20000u) && ((pk & 0xFFFFu) == (unsigned)s));
        while (match) {
            int bl = __ffs(match) - 1;
            match &= match - 1;
            unsigned pkb = __shfl_sync(FULLM, pk, bl);
            float alpha = (pkb & 0x10000u) ? 0.9f : 0.3f;
            float om = 1.0f - alpha;
            int t = base + bl;
            const float* kr = &g_k[t * DIM];
            const float* vr = &g_v[t * DIM];
#pragma unroll
            for (int r = 0; r < 8; r++) {
                kreg[r] = om * kreg[r] + alpha * __ldg(&kr[lane + 32 * r]);
                vreg[r] = om * vreg[r] + alpha * __ldg(&vr[lane + 32 * r]);
            }
        }
    }
#pragma unroll
    for (int r = 0; r < 8; r++) {
        g_kb[s * DIM + lane + 32 * r] = kreg[r];
        g_vb[s * DIM + lane + 32 * r] = vreg[r];
    }
}

// ------- 6) fused read attention (flash-style online softmax) ------------
#define QP 260
#define KP 257
#define VP 260
#define PP 68
__global__ __launch_bounds__(256) void attn_kernel(float* __restrict__ out)
{
    extern __shared__ float sm[];
    float* Qs = sm;                    // 64 x QP
    float* Bb = Qs + 64 * QP;          // 64 x max(KP,VP)
    float* Ps = Bb + 64 * VP;          // 64 x PP
    float* lact = Ps + 64 * PP;        // 64

    int tid = threadIdx.x;
    int tx = tid & 15, ty = tid >> 4;
    int t0 = blockIdx.x * 64;

    for (int idx = tid; idx < 64 * 64; idx += 256) {
        int row = idx >> 6, c4 = (idx & 63) * 4;
        float4 v = *(const float4*)&g_q[(t0 + row) * DIM + c4];
        *(float4*)&Qs[row * QP + c4] = v;
    }

    float m_i[4], l_i[4], O[4][16];
#pragma unroll
    for (int r = 0; r < 4; r++) {
        m_i[r] = -1e30f; l_i[r] = 0.f;
#pragma unroll
        for (int e = 0; e < 16; e++) O[r][e] = 0.f;
    }

    for (int n0 = 0; n0 < NSLOT; n0 += 64) {
        __syncthreads();
        if (tid < 64) {
            float a = g_act[n0 + tid];
            lact[tid] = (a < 0.01f) ? -1e30f : logf(a);
        }
        for (int idx = tid; idx < 64 * 64; idx += 256) {
            int row = idx >> 6, c4 = (idx & 63) * 4;
            float4 v = *(const float4*)&g_kb[(n0 + row) * DIM + c4];
            float* p = &Bb[row * KP + c4];
            p[0] = v.x; p[1] = v.y; p[2] = v.z; p[3] = v.w;
        }
        __syncthreads();

        float S[4][4];
#pragma unroll
        for (int r = 0; r < 4; r++)
#pragma unroll
            for (int c = 0; c < 4; c++) S[r][c] = 0.f;
#pragma unroll 8
        for (int k = 0; k < DIM; k++) {
            float a[4], bb[4];
#pragma unroll
            for (int r = 0; r < 4; r++) a[r] = Qs[(ty * 4 + r) * QP + k];
#pragma unroll
            for (int c = 0; c < 4; c++) bb[c] = Bb[(tx * 4 + c) * KP + k];
#pragma unroll
            for (int r = 0; r < 4; r++)
#pragma unroll
                for (int c = 0; c < 4; c++) S[r][c] += a[r] * bb[c];
        }
#pragma unroll
        for (int r = 0; r < 4; r++) {
            float srow[4]; float rmax = -1e30f;
#pragma unroll
            for (int c = 0; c < 4; c++) {
                srow[c] = S[r][c] * 0.0625f + lact[tx * 4 + c];
                rmax = fmaxf(rmax, srow[c]);
            }
#pragma unroll
            for (int o = 1; o < 16; o <<= 1)
                rmax = fmaxf(rmax, __shfl_xor_sync(FULLM, rmax, o));
            float mn = fmaxf(m_i[r], rmax);
            float corr = __expf(m_i[r] - mn);
            float ps = 0.f;
#pragma unroll
            for (int c = 0; c < 4; c++) {
                float p = __expf(srow[c] - mn);
                ps += p;
                Ps[(ty * 4 + r) * PP + tx * 4 + c] = p;
            }
#pragma unroll
            for (int o = 1; o < 16; o <<= 1)
                ps += __shfl_xor_sync(FULLM, ps, o);
            l_i[r] = l_i[r] * corr + ps;
            m_i[r] = mn;
#pragma unroll
            for (int e = 0; e < 16; e++) O[r][e] *= corr;
        }
        __syncthreads();

        for (int idx = tid; idx < 64 * 64; idx += 256) {
            int row = idx >> 6, c4 = (idx & 63) * 4;
            float4 v = *(const float4*)&g_vb[(n0 + row) * DIM + c4];
            *(float4*)&Bb[row * VP + c4] = v;
        }
        __syncthreads();

#pragma unroll 2
        for (int j = 0; j < 64; j++) {
            float pj[4];
#pragma unroll
            for (int r = 0; r < 4; r++) pj[r] = Ps[(ty * 4 + r) * PP + j];
            float4 v0 = *(const float4*)&Bb[j * VP + tx * 4];
            float4 v1 = *(const float4*)&Bb[j * VP + tx * 4 + 64];
            float4 v2 = *(const float4*)&Bb[j * VP + tx * 4 + 128];
            float4 v3 = *(const float4*)&Bb[j * VP + tx * 4 + 192];
#pragma unroll
            for (int r = 0; r < 4; r++) {
                O[r][0]  += pj[r] * v0.x; O[r][1]  += pj[r] * v0.y;
                O[r][2]  += pj[r] * v0.z; O[r][3]  += pj[r] * v0.w;
                O[r][4]  += pj[r] * v1.x; O[r][5]  += pj[r] * v1.y;
                O[r][6]  += pj[r] * v1.z; O[r][7]  += pj[r] * v1.w;
                O[r][8]  += pj[r] * v2.x; O[r][9]  += pj[r] * v2.y;
                O[r][10] += pj[r] * v2.z; O[r][11] += pj[r] * v2.w;
                O[r][12] += pj[r] * v3.x; O[r][13] += pj[r] * v3.y;
                O[r][14] += pj[r] * v3.z; O[r][15] += pj[r] * v3.w;
            }
        }
    }
#pragma unroll
    for (int r = 0; r < 4; r++) {
        float inv = 1.0f / l_i[r];
        int trow = (t0 + ty * 4 + r) * DIM;
#pragma unroll
        for (int q = 0; q < 4; q++) {
            float4 o4 = make_float4(O[r][q * 4 + 0] * inv, O[r][q * 4 + 1] * inv,
                                    O[r][q * 4 + 2] * inv, O[r][q * 4 + 3] * inv);
            *(float4*)&out[trow + tx * 4 + 64 * q] = o4;
        }
    }
}

// --------------------------------- launch --------------------------------
extern "C" void kernel_launch(void* const* d_in, const int* in_sizes, int n_in,
                              void* d_out, int out_size)
{
    const float* x     = (const float*)d_in[0];
    const void*  wmask = d_in[1];
    const float* keys0 = (const float*)d_in[2];
    const float* vals0 = (const float*)d_in[3];
    const float* act0  = (const float*)d_in[4];
    const float* Wk    = (const float*)d_in[5];
    const float* bk    = (const float*)d_in[6];
    const float* Wv    = (const float*)d_in[7];
    const float* bv    = (const float*)d_in[8];
    const float* Wq    = (const float*)d_in[9];
    const float* bq    = (const float*)d_in[10];
    float* out = (float*)d_out;

    size_t attn_smem = (size_t)(64 * QP + 64 * VP + 64 * PP + 64) * sizeof(float);
    static bool attr_done = false;
    if (!attr_done) {
        cudaFuncSetAttribute(attn_kernel,
                             cudaFuncAttributeMaxDynamicSharedMemorySize,
                             (int)attn_smem);
        attr_done = true;
    }

    proj_kernel<<<dim3(T_TOK / 64, DIM / 64, 3), 256>>>(x, Wk, bk, Wv, bv, Wq, bq);
    simmax_kernel<<<dim3(T_TOK / 64, 4), 256>>>(keys0);
    combine_kernel<<<T_TOK / 256, 256>>>(wmask);
    scan_kernel<<<1, 256>>>(act0);
    rebuild_kernel<<<NSLOT / 8, 256>>>(keys0, vals0);
    attn_kernel<<<T_TOK / 64, 256, attn_smem>>>(out);
}

// round 3
// speedup vs baseline: 1.2044x; 1.2044x over previous
#include <cuda_runtime.h>
#include <cuda_bf16.h>
#include <math_constants.h>

#define T_TOK 8192
#define DIM   256
#define NSLOT 4096
#define FULLM 0xffffffffu
#define GPAD  136          // smem row pitch (floats) for a 128-wide tile
#define BK    16

typedef unsigned long long ull;

// ---------------- scratch (device globals; no allocation) ----------------
__device__ float g_k[T_TOK * DIM];
__device__ float g_v[T_TOK * DIM];
__device__ float g_q[T_TOK * DIM];
__device__ float g_pmax[32 * T_TOK];
__device__ int   g_pidx[32 * T_TOK];
__device__ unsigned g_info[T_TOK];     // best | novel<<16 | m<<17
__device__ unsigned g_pick[T_TOK];     // slot | novel<<16 | applied<<17
__device__ float g_act[NSLOT];
__device__ float g_lb[NSLOT];
__device__ float g_kb[NSLOT * DIM];
__device__ float g_vb[NSLOT * DIM];
__device__ float g_rowsum[T_TOK];
__device__ float g_S[(size_t)T_TOK * NSLOT];   // 134MB logits/exp buffer

// ---------------- f32x2 helpers ------------------------------------------
__device__ __forceinline__ ull dupf(float b) {
    ull r;
    asm("mov.b64 %0, {%1, %1};" : "=l"(r) : "f"(b));
    return r;
}
__device__ __forceinline__ void fma2(ull& d, ull a, ull b) {
    asm("fma.rn.f32x2 %0, %1, %2, %0;" : "+l"(d) : "l"(a), "l"(b));
}
__device__ __forceinline__ float2 up2(ull u) {
    float2 f;
    asm("mov.b64 {%0, %1}, %2;" : "=f"(f.x), "=f"(f.y) : "l"(u));
    return f;
}

// ---------------- generic 128x128 f32x2 GEMM mainloop ---------------------
// A: gmem, row-major [128 rows][K], k contiguous (pre-offset to tile row 0)
// B (BDIRECT=false): gmem row-major [128 rows][K]  -> smem transposed [k][n]
// B (BDIRECT=true) : gmem row-major [K][ldb], pre-offset to col 0 of tile
// acc[rp][c] packs output rows (ty*8+2rp, ty*8+2rp+1), col = tx*8+c.
template<bool BDIRECT>
__device__ __forceinline__ void gemm128(
    const float* __restrict__ A, const float* __restrict__ B,
    int lda, int ldb, int K, ull acc[4][8], float* sA, float* sB, int tid)
{
    const int tx = tid & 15, ty = tid >> 4;
    const int arow = tid >> 1;          // 0..127
    const int akb  = (tid & 1) * 8;     // 0 or 8
    const int bkr  = tid >> 4;          // 0..15 (direct-B)
    const int bnc  = (tid & 15) * 8;    // 0..120 (direct-B)

#pragma unroll
    for (int rp = 0; rp < 4; rp++)
#pragma unroll
        for (int c = 0; c < 8; c++) acc[rp][c] = 0ull;

    // prologue: chunk 0 -> smem
    {
        float4 ra0 = *(const float4*)&A[arow * lda + akb];
        float4 ra1 = *(const float4*)&A[arow * lda + akb + 4];
        sA[(akb + 0) * GPAD + arow] = ra0.x; sA[(akb + 1) * GPAD + arow] = ra0.y;
        sA[(akb + 2) * GPAD + arow] = ra0.z; sA[(akb + 3) * GPAD + arow] = ra0.w;
        sA[(akb + 4) * GPAD + arow] = ra1.x; sA[(akb + 5) * GPAD + arow] = ra1.y;
        sA[(akb + 6) * GPAD + arow] = ra1.z; sA[(akb + 7) * GPAD + arow] = ra1.w;
        if (BDIRECT) {
            float4 rb0 = *(const float4*)&B[bkr * ldb + bnc];
            float4 rb1 = *(const float4*)&B[bkr * ldb + bnc + 4];
            *(float4*)&sB[bkr * GPAD + bnc]     = rb0;
            *(float4*)&sB[bkr * GPAD + bnc + 4] = rb1;
        } else {
            float4 rb0 = *(const float4*)&B[arow * ldb + akb];
            float4 rb1 = *(const float4*)&B[arow * ldb + akb + 4];
            sB[(akb + 0) * GPAD + arow] = rb0.x; sB[(akb + 1) * GPAD + arow] = rb0.y;
            sB[(akb + 2) * GPAD + arow] = rb0.z; sB[(akb + 3) * GPAD + arow] = rb0.w;
            sB[(akb + 4) * GPAD + arow] = rb1.x; sB[(akb + 5) * GPAD + arow] = rb1.y;
            sB[(akb + 6) * GPAD + arow] = rb1.z; sB[(akb + 7) * GPAD + arow] = rb1.w;
        }
    }
    __syncthreads();

    for (int kk = 0; kk < K; kk += BK) {
        const bool more = (kk + BK) < K;
        float4 ra0, ra1, rb0, rb1;
        if (more) {
            ra0 = *(const float4*)&A[arow * lda + kk + BK + akb];
            ra1 = *(const float4*)&A[arow * lda + kk + BK + akb + 4];
            if (BDIRECT) {
                rb0 = *(const float4*)&B[(kk + BK + bkr) * ldb + bnc];
                rb1 = *(const float4*)&B[(kk + BK + bkr) * ldb + bnc + 4];
            } else {
                rb0 = *(const float4*)&B[arow * ldb + kk + BK + akb];
                rb1 = *(const float4*)&B[arow * ldb + kk + BK + akb + 4];
            }
        }
        // compute on resident chunk
#pragma unroll
        for (int kc = 0; kc < BK; kc++) {
            const float* ar = sA + kc * GPAD + ty * 8;
            ull a0 = *(const ull*)(ar + 0);
            ull a1 = *(const ull*)(ar + 2);
            ull a2 = *(const ull*)(ar + 4);
            ull a3 = *(const ull*)(ar + 6);
            const float* br = sB + kc * GPAD + tx * 8;
#pragma unroll
            for (int c = 0; c < 8; c++) {
                ull bd = dupf(br[c]);
                fma2(acc[0][c], a0, bd);
                fma2(acc[1][c], a1, bd);
                fma2(acc[2][c], a2, bd);
                fma2(acc[3][c], a3, bd);
            }
        }
        __syncthreads();
        if (more) {
            sA[(akb + 0) * GPAD + arow] = ra0.x; sA[(akb + 1) * GPAD + arow] = ra0.y;
            sA[(akb + 2) * GPAD + arow] = ra0.z; sA[(akb + 3) * GPAD + arow] = ra0.w;
            sA[(akb + 4) * GPAD + arow] = ra1.x; sA[(akb + 5) * GPAD + arow] = ra1.y;
            sA[(akb + 6) * GPAD + arow] = ra1.z; sA[(akb + 7) * GPAD + arow] = ra1.w;
            if (BDIRECT) {
                *(float4*)&sB[bkr * GPAD + bnc]     = rb0;
                *(float4*)&sB[bkr * GPAD + bnc + 4] = rb1;
            } else {
                sB[(akb + 0) * GPAD + arow] = rb0.x; sB[(akb + 1) * GPAD + arow] = rb0.y;
                sB[(akb + 2) * GPAD + arow] = rb0.z; sB[(akb + 3) * GPAD + arow] = rb0.w;
                sB[(akb + 4) * GPAD + arow] = rb1.x; sB[(akb + 5) * GPAD + arow] = rb1.y;
                sB[(akb + 6) * GPAD + arow] = rb1.z; sB[(akb + 7) * GPAD + arow] = rb1.w;
            }
            __syncthreads();
        }
    }
}

// ---------------- 1) projections -----------------------------------------
__global__ __launch_bounds__(256, 2) void proj_kernel(
    const float* __restrict__ x,
    const float* __restrict__ Wk, const float* __restrict__ bk,
    const float* __restrict__ Wv, const float* __restrict__ bv,
    const float* __restrict__ Wq, const float* __restrict__ bq)
{
    __shared__ float sA[BK * GPAD];
    __shared__ float sB[BK * GPAD];
    const float* W; const float* bvec; float* out;
    if (blockIdx.z == 0)      { W = Wk; bvec = bk; out = g_k; }
    else if (blockIdx.z == 1) { W = Wv; bvec = bv; out = g_v; }
    else                      { W = Wq; bvec = bq; out = g_q; }

    int tid = threadIdx.x;
    int m0 = blockIdx.x * 128, n0 = blockIdx.y * 128;
    ull acc[4][8];
    gemm128<false>(x + (size_t)m0 * DIM, W + (size_t)n0 * DIM, DIM, DIM, DIM,
                   acc, sA, sB, tid);
    int tx = tid & 15, ty = tid >> 4;
    int col0 = n0 + tx * 8;
    float bb[8];
#pragma unroll
    for (int c = 0; c < 8; c++) bb[c] = bvec[col0 + c];
#pragma unroll
    for (int rp = 0; rp < 4; rp++) {
        int row = m0 + ty * 8 + 2 * rp;
        float v0[8], v1[8];
#pragma unroll
        for (int c = 0; c < 8; c++) {
            float2 f = up2(acc[rp][c]);
            v0[c] = f.x + bb[c];
            v1[c] = f.y + bb[c];
        }
        *(float4*)&out[(size_t)row * DIM + col0]         = make_float4(v0[0], v0[1], v0[2], v0[3]);
        *(float4*)&out[(size_t)row * DIM + col0 + 4]     = make_float4(v0[4], v0[5], v0[6], v0[7]);
        *(float4*)&out[(size_t)(row + 1) * DIM + col0]     = make_float4(v1[0], v1[1], v1[2], v1[3]);
        *(float4*)&out[(size_t)(row + 1) * DIM + col0 + 4] = make_float4(v1[4], v1[5], v1[6], v1[7]);
    }
}

// ---------------- 2) simmax: per-token max/argmax partials ----------------
__global__ __launch_bounds__(256, 2) void simmax_kernel(const float* __restrict__ keys0)
{
    __shared__ float sA[BK * GPAD];
    __shared__ float sB[BK * GPAD];
    int tid = threadIdx.x;
    int m0 = blockIdx.x * 128, n0 = blockIdx.y * 128;
    ull acc[4][8];
    gemm128<false>(g_k + (size_t)m0 * DIM, keys0 + (size_t)n0 * DIM, DIM, DIM, DIM,
                   acc, sA, sB, tid);
    int tx = tid & 15, ty = tid >> 4;
#pragma unroll
    for (int r = 0; r < 8; r++) {
        float best = -CUDART_INF_F; int bi = 0x7fffffff;
#pragma unroll
        for (int c = 0; c < 8; c++) {
            float2 f = up2(acc[r >> 1][c]);
            float v = (r & 1) ? f.y : f.x;
            if (v > best) { best = v; bi = n0 + tx * 8 + c; }
        }
#pragma unroll
        for (int o = 1; o < 16; o <<= 1) {
            float ov = __shfl_xor_sync(FULLM, best, o);
            int   oi = __shfl_xor_sync(FULLM, bi, o);
            if (ov > best || (ov == best && oi < bi)) { best = ov; bi = oi; }
        }
        if (tx == 0) {
            int t = m0 + ty * 8 + r;
            g_pmax[blockIdx.y * T_TOK + t] = best;
            g_pidx[blockIdx.y * T_TOK + t] = bi;
        }
    }
}

// ---------------- 3) combine segments -> g_info ---------------------------
__global__ void combine_kernel(const void* __restrict__ maskptr)
{
    int t = blockIdx.x * blockDim.x + threadIdx.x;
    if (t >= T_TOK) return;
    float best = -CUDART_INF_F; int bi = 0;
#pragma unroll
    for (int s = 0; s < 32; s++) {
        float v = g_pmax[s * T_TOK + t];
        int   i = g_pidx[s * T_TOK + t];
        if (v > best) { best = v; bi = i; }   // segments ascend in index
    }
    bool novel = (best * 0.0625f) < 0.5f;
    const unsigned* w = (const unsigned*)maskptr;
    bool bytemode = (w[0] == 0x01010101u);
    bool m;
    if (bytemode) m = ((const unsigned char*)maskptr)[t] != 0;
    else          m = (w[t] != 0);
    g_info[t] = (unsigned)bi | (novel ? 0x10000u : 0u) | (m ? 0x20000u : 0u);
}

// ---------------- 4) sequential scan (unchanged) --------------------------
__global__ __launch_bounds__(256) void scan_kernel(const float* __restrict__ act0)
{
    __shared__ __align__(16) float s_act[NSLOT];
    __shared__ __align__(16) float s_gmin[128];
    __shared__ int s_gidx[128];
    int tid = threadIdx.x;
    for (int i = tid; i < NSLOT; i += 256) s_act[i] = act0[i];
    __syncthreads();
    int wid = tid >> 5, lane = tid & 31;
    for (int g = wid; g < 128; g += 8) {
        float v = s_act[g * 32 + lane];
        unsigned mv = __reduce_min_sync(FULLM, __float_as_uint(v));
        unsigned bal = __ballot_sync(FULLM, __float_as_uint(v) == mv);
        if (lane == 0) { s_gmin[g] = __uint_as_float(mv); s_gidx[g] = g * 32 + (__ffs(bal) - 1); }
    }
    __syncthreads();

    if (wid == 0) {
        unsigned myinfo = 0;
        for (int t = 0; t < T_TOK; t++) {
            if ((t & 31) == 0) myinfo = __ldg(&g_info[t + lane]);
            unsigned info = __shfl_sync(FULLM, myinfo, t & 31);
            if (info & 0x20000u) {
                int slot;
                if (info & 0x10000u) {
                    float4 q4 = *(const float4*)&s_gmin[lane * 4];
                    float bv = q4.x; int bg = lane * 4;
                    if (q4.y < bv) { bv = q4.y; bg = lane * 4 + 1; }
                    if (q4.z < bv) { bv = q4.z; bg = lane * 4 + 2; }
                    if (q4.w < bv) { bv = q4.w; bg = lane * 4 + 3; }
                    unsigned mv = __reduce_min_sync(FULLM, __float_as_uint(bv));
                    unsigned bal = __ballot_sync(FULLM, __float_as_uint(bv) == mv);
                    int L = __ffs(bal) - 1;
                    int grp = __shfl_sync(FULLM, bg, L);
                    slot = s_gidx[grp];
                } else {
                    slot = (int)(info & 0xFFFFu);
                }
                float na = fminf(1.0f, s_act[slot] + 0.1f);
                if (lane == 0) s_act[slot] = na;
                __syncwarp();
                int g = slot >> 5;
                float v = s_act[g * 32 + lane];
                unsigned mv2 = __reduce_min_sync(FULLM, __float_as_uint(v));
                unsigned bal2 = __ballot_sync(FULLM, __float_as_uint(v) == mv2);
                if (lane == 0) {
                    s_gmin[g] = __uint_as_float(mv2);
                    s_gidx[g] = g * 32 + (__ffs(bal2) - 1);
                    g_pick[t] = (unsigned)slot | (info & 0x10000u) | 0x20000u;
                }
                __syncwarp();
            } else {
                if (lane == 0) g_pick[t] = 0u;
            }
        }
    }
    __syncthreads();
    for (int i = tid; i < NSLOT; i += 256) g_act[i] = s_act[i];
}

// ---------------- 5) rebuild kb/vb (unchanged) ----------------------------
__global__ __launch_bounds__(256) void rebuild_kernel(
    const float* __restrict__ keys0, const float* __restrict__ values0)
{
    int wid = threadIdx.x >> 5, lane = threadIdx.x & 31;
    int s = blockIdx.x * 8 + wid;
    float kreg[8], vreg[8];
#pragma unroll
    for (int r = 0; r < 8; r++) {
        kreg[r] = keys0[s * DIM + lane + 32 * r];
        vreg[r] = values0[s * DIM + lane + 32 * r];
    }
    for (int base = 0; base < T_TOK; base += 32) {
        unsigned pk = __ldg(&g_pick[base + lane]);
        unsigned match = __ballot_sync(FULLM,
            (pk & 0x20000u) && ((pk & 0xFFFFu) == (unsigned)s));
        while (match) {
            int bl = __ffs(match) - 1;
            match &= match - 1;
            unsigned pkb = __shfl_sync(FULLM, pk, bl);
            float alpha = (pkb & 0x10000u) ? 0.9f : 0.3f;
            float om = 1.0f - alpha;
            int t = base + bl;
            const float* kr = &g_k[(size_t)t * DIM];
            const float* vr = &g_v[(size_t)t * DIM];
#pragma unroll
            for (int r = 0; r < 8; r++) {
                kreg[r] = om * kreg[r] + alpha * __ldg(&kr[lane + 32 * r]);
                vreg[r] = om * vreg[r] + alpha * __ldg(&vr[lane + 32 * r]);
            }
        }
    }
#pragma unroll
    for (int r = 0; r < 8; r++) {
        g_kb[s * DIM + lane + 32 * r] = kreg[r];
        g_vb[s * DIM + lane + 32 * r] = vreg[r];
    }
}

// ---------------- 5b) activation bias -------------------------------------
__global__ void actbias_kernel()
{
    int n = blockIdx.x * blockDim.x + threadIdx.x;
    if (n >= NSLOT) return;
    float a = g_act[n];
    g_lb[n] = (a < 0.01f) ? -1e30f : logf(a);
}

// ---------------- 6a) attnA: S = q@kb^T*scale + lbias, row-max partials ---
__global__ __launch_bounds__(256, 2) void attnA_kernel()
{
    __shared__ float sA[BK * GPAD];
    __shared__ float sB[BK * GPAD];
    int tid = threadIdx.x;
    int m0 = blockIdx.x * 128, n0 = blockIdx.y * 128;
    ull acc[4][8];
    gemm128<false>(g_q + (size_t)m0 * DIM, g_kb + (size_t)n0 * DIM, DIM, DIM, DIM,
                   acc, sA, sB, tid);
    int tx = tid & 15, ty = tid >> 4;
    int col0 = n0 + tx * 8;
    float lbv[8];
#pragma unroll
    for (int c = 0; c < 8; c++) lbv[c] = g_lb[col0 + c];
#pragma unroll
    for (int r = 0; r < 8; r++) {
        int row = m0 + ty * 8 + r;
        float v[8]; float rmax = -CUDART_INF_F;
#pragma unroll
        for (int c = 0; c < 8; c++) {
            float2 f = up2(acc[r >> 1][c]);
            float s = ((r & 1) ? f.y : f.x) * 0.0625f + lbv[c];
            v[c] = s;
            rmax = fmaxf(rmax, s);
        }
        *(float4*)&g_S[(size_t)row * NSLOT + col0]     = make_float4(v[0], v[1], v[2], v[3]);
        *(float4*)&g_S[(size_t)row * NSLOT + col0 + 4] = make_float4(v[4], v[5], v[6], v[7]);
#pragma unroll
        for (int o = 1; o < 16; o <<= 1)
            rmax = fmaxf(rmax, __shfl_xor_sync(FULLM, rmax, o));
        if (tx == 0) g_pmax[blockIdx.y * T_TOK + row] = rmax;
    }
}

// ---------------- 6b) attnB: E = exp(S - m), row sums ---------------------
__global__ __launch_bounds__(256) void attnB_kernel()
{
    int tid = threadIdx.x;
    int w = tid >> 5, lane = tid & 31;
    int rbase = blockIdx.x * 64 + w * 8;
#pragma unroll
    for (int rr = 0; rr < 8; rr++) {
        int row = rbase + rr;
        float m = g_pmax[lane * T_TOK + row];
#pragma unroll
        for (int o = 16; o > 0; o >>= 1)
            m = fmaxf(m, __shfl_xor_sync(FULLM, m, o));
        float* Sr = &g_S[(size_t)row * NSLOT];
        float sum = 0.f;
#pragma unroll 4
        for (int q = 0; q < 32; q++) {
            float4 v = *(float4*)&Sr[lane * 4 + q * 128];
            v.x = __expf(v.x - m); v.y = __expf(v.y - m);
            v.z = __expf(v.z - m); v.w = __expf(v.w - m);
            *(float4*)&Sr[lane * 4 + q * 128] = v;
            sum += v.x + v.y + v.z + v.w;
        }
#pragma unroll
        for (int o = 16; o > 0; o >>= 1)
            sum += __shfl_xor_sync(FULLM, sum, o);
        if (lane == 0) g_rowsum[row] = sum;
    }
}

// ---------------- 6c) attnC: O = (E @ vb) / rowsum -------------------------
__global__ __launch_bounds__(256, 2) void attnC_kernel(float* __restrict__ out)
{
    __shared__ float sA[BK * GPAD];
    __shared__ float sB[BK * GPAD];
    int tid = threadIdx.x;
    int m0 = blockIdx.x * 128, n0 = blockIdx.y * 128;
    ull acc[4][8];
    gemm128<true>(g_S + (size_t)m0 * NSLOT, g_vb + n0, NSLOT, DIM, NSLOT,
                  acc, sA, sB, tid);
    int tx = tid & 15, ty = tid >> 4;
    int col0 = n0 + tx * 8;
#pragma unroll
    for (int rp = 0; rp < 4; rp++) {
        int row = m0 + ty * 8 + 2 * rp;
        float inv0 = 1.0f / g_rowsum[row];
        float inv1 = 1.0f / g_rowsum[row + 1];
        float v0[8], v1[8];
#pragma unroll
        for (int c = 0; c < 8; c++) {
            float2 f = up2(acc[rp][c]);
            v0[c] = f.x * inv0;
            v1[c] = f.y * inv1;
        }
        *(float4*)&out[(size_t)row * DIM + col0]           = make_float4(v0[0], v0[1], v0[2], v0[3]);
        *(float4*)&out[(size_t)row * DIM + col0 + 4]       = make_float4(v0[4], v0[5], v0[6], v0[7]);
        *(float4*)&out[(size_t)(row + 1) * DIM + col0]     = make_float4(v1[0], v1[1], v1[2], v1[3]);
        *(float4*)&out[(size_t)(row + 1) * DIM + col0 + 4] = make_float4(v1[4], v1[5], v1[6], v1[7]);
    }
}

// --------------------------------- launch --------------------------------
extern "C" void kernel_launch(void* const* d_in, const int* in_sizes, int n_in,
                              void* d_out, int out_size)
{
    const float* x     = (const float*)d_in[0];
    const void*  wmask = d_in[1];
    const float* keys0 = (const float*)d_in[2];
    const float* vals0 = (const float*)d_in[3];
    const float* act0  = (const float*)d_in[4];
    const float* Wk    = (const float*)d_in[5];
    const float* bk    = (const float*)d_in[6];
    const float* Wv    = (const float*)d_in[7];
    const float* bv    = (const float*)d_in[8];
    const float* Wq    = (const float*)d_in[9];
    const float* bq    = (const float*)d_in[10];
    float* out = (float*)d_out;

    proj_kernel<<<dim3(T_TOK / 128, DIM / 128, 3), 256>>>(x, Wk, bk, Wv, bv, Wq, bq);
    simmax_kernel<<<dim3(T_TOK / 128, NSLOT / 128), 256>>>(keys0);
    combine_kernel<<<T_TOK / 256, 256>>>(wmask);
    scan_kernel<<<1, 256>>>(act0);
    rebuild_kernel<<<NSLOT / 8, 256>>>(keys0, vals0);
    actbias_kernel<<<NSLOT / 256, 256>>>();
    attnA_kernel<<<dim3(T_TOK / 128, NSLOT / 128), 256>>>();
    attnB_kernel<<<T_TOK / 64, 256>>>();
    attnC_kernel<<<dim3(T_TOK / 128, DIM / 128), 256>>>(out);
}